// round 1
// baseline (speedup 1.0000x reference)
#include <cuda_runtime.h>
#include <cstdint>
#include <cstddef>

// Problem constants
#define B_   2048
#define E_   512
#define EMB_ 256
#define AR_  1024
#define H256_ 256
#define H32_  32
#define NT_   256

// Scratch (no cudaMalloc allowed)
__device__ float g_M[B_ * H256_];    // z1 = relu(mask@W_func+b_func) + ar@W_fc1 + b_fc1
__device__ float g_w[B_ * EMB_];     // per-b folded weight: W_conv @ query[b]
__device__ float g_c0[B_];           // b_conv . query[b]

// ---------------------------------------------------------------------------
// Threefry2x32-20, JAX partitionable variant: counter = (hi=0, lo=index),
// 32-bit output = out0 ^ out1. Key = jax.random.key(42) = (0, 42).
// ---------------------------------------------------------------------------
__device__ __forceinline__ uint32_t rotl32(uint32_t x, int r) {
    return (x << r) | (x >> (32 - r));
}

__device__ __forceinline__ uint32_t threefry_bits(uint32_t k0, uint32_t k1,
                                                  uint32_t c0, uint32_t c1) {
    uint32_t ks2 = k0 ^ k1 ^ 0x1BD11BDAu;
    uint32_t x0 = c0 + k0;
    uint32_t x1 = c1 + k1;
#define TF_RND(r) { x0 += x1; x1 = rotl32(x1, (r)); x1 ^= x0; }
    TF_RND(13) TF_RND(15) TF_RND(26) TF_RND(6)
    x0 += k1;  x1 += ks2 + 1u;
    TF_RND(17) TF_RND(29) TF_RND(16) TF_RND(24)
    x0 += ks2; x1 += k0 + 2u;
    TF_RND(13) TF_RND(15) TF_RND(26) TF_RND(6)
    x0 += k0;  x1 += k1 + 3u;
    TF_RND(17) TF_RND(29) TF_RND(16) TF_RND(24)
    x0 += k1;  x1 += ks2 + 4u;
    TF_RND(13) TF_RND(15) TF_RND(26) TF_RND(6)
    x0 += ks2; x1 += k0 + 5u;
#undef TF_RND
    return x0 ^ x1;
}

__device__ __forceinline__ float gumbel_from_index(uint32_t idx) {
    uint32_t bits = threefry_bits(0u, 42u, 0u, idx);
    // jax uniform(minval=tiny, maxval=1): u = bitcast(bits>>9 | 0x3f800000) - 1
    // then u*(1-tiny)+tiny with (1-tiny)==1 in fp32 -> u + tiny, then max(tiny, .)
    float u = __uint_as_float((bits >> 9) | 0x3f800000u) - 1.0f;
    const float tiny = 1.17549435e-38f;
    u = fmaxf(tiny, u + tiny);
    return -logf(-logf(u));
}

// ---------------------------------------------------------------------------
// Kernel A1: g_M[b,j] = relu(maskf[b,:] @ W_func + b_func)[j]
//                     + (ar[b,:] @ W_fc1 + b_fc1)[j]
// Tiled fp32 GEMM: BM=64, BN=64, BK=16, 256 threads, 4x4 micro-tile.
// ---------------------------------------------------------------------------
__global__ __launch_bounds__(256)
void kernelA1(const float* __restrict__ ar, const int* __restrict__ utm,
              const float* __restrict__ W_func, const float* __restrict__ b_func,
              const float* __restrict__ W_fc1, const float* __restrict__ b_fc1) {
    __shared__ float As[16][68];   // [k][m], padded
    __shared__ float Bs[16][64];   // [k][n]

    const int bm = blockIdx.x * 64;
    const int bn = blockIdx.y * 64;
    const int tid = threadIdx.x;
    const int tx = tid & 15;       // n group
    const int ty = tid >> 4;       // m group

    const int lAm = tid >> 2;            // 0..63
    const int lAk = (tid & 3) * 4;       // 0,4,8,12
    const int lBk = tid >> 4;            // 0..15
    const int lBn = (tid & 15) * 4;      // 0..60

    float acc[4][4];
    float keep[4][4];
#pragma unroll
    for (int i = 0; i < 4; i++)
#pragma unroll
        for (int j = 0; j < 4; j++) acc[i][j] = 0.0f;

    // ---- Phase 1: mask @ W_func, K = 256 ----
    for (int k0 = 0; k0 < NT_; k0 += 16) {
        int4 mi = *(const int4*)(utm + (bm + lAm) * NT_ + k0 + lAk);
        As[lAk + 0][lAm] = (float)mi.x;
        As[lAk + 1][lAm] = (float)mi.y;
        As[lAk + 2][lAm] = (float)mi.z;
        As[lAk + 3][lAm] = (float)mi.w;
        *(float4*)&Bs[lBk][lBn] = *(const float4*)(W_func + (k0 + lBk) * H256_ + bn + lBn);
        __syncthreads();
#pragma unroll
        for (int kk = 0; kk < 16; kk++) {
            float a[4], bb[4];
            *(float4*)a  = *(const float4*)&As[kk][ty * 4];
            *(float4*)bb = *(const float4*)&Bs[kk][tx * 4];
#pragma unroll
            for (int i = 0; i < 4; i++)
#pragma unroll
                for (int j = 0; j < 4; j++) acc[i][j] += a[i] * bb[j];
        }
        __syncthreads();
    }
    // bias + relu, stash; reset accumulators for phase 2
#pragma unroll
    for (int j = 0; j < 4; j++) {
        float bf = b_func[bn + tx * 4 + j];
#pragma unroll
        for (int i = 0; i < 4; i++) {
            keep[i][j] = fmaxf(acc[i][j] + bf, 0.0f);
            acc[i][j] = 0.0f;
        }
    }

    // ---- Phase 2: ar @ W_fc1, K = 1024 ----
    for (int k0 = 0; k0 < AR_; k0 += 16) {
        float4 av = *(const float4*)(ar + (bm + lAm) * AR_ + k0 + lAk);
        As[lAk + 0][lAm] = av.x;
        As[lAk + 1][lAm] = av.y;
        As[lAk + 2][lAm] = av.z;
        As[lAk + 3][lAm] = av.w;
        *(float4*)&Bs[lBk][lBn] = *(const float4*)(W_fc1 + (k0 + lBk) * H256_ + bn + lBn);
        __syncthreads();
#pragma unroll
        for (int kk = 0; kk < 16; kk++) {
            float a[4], bb[4];
            *(float4*)a  = *(const float4*)&As[kk][ty * 4];
            *(float4*)bb = *(const float4*)&Bs[kk][tx * 4];
#pragma unroll
            for (int i = 0; i < 4; i++)
#pragma unroll
                for (int j = 0; j < 4; j++) acc[i][j] += a[i] * bb[j];
        }
        __syncthreads();
    }

#pragma unroll
    for (int j = 0; j < 4; j++) {
        float bx = b_fc1[bn + tx * 4 + j];
#pragma unroll
        for (int i = 0; i < 4; i++) {
            g_M[(bm + ty * 4 + i) * H256_ + bn + tx * 4 + j] = keep[i][j] + acc[i][j] + bx;
        }
    }
}

// ---------------------------------------------------------------------------
// Kernel A2: per-b: z2 = M[b]@W_fc2 + b_fc2 ; LSTM step with h0=c0=0 ;
//            query = sigmoid(o)*tanh(sigmoid(i)*tanh(g)) ;
//            g_w[b] = W_conv @ query ; g_c0[b] = b_conv . query
// One warp per b. 8 warps per block.
// ---------------------------------------------------------------------------
__global__ __launch_bounds__(256)
void kernelA2(const float* __restrict__ W_fc2, const float* __restrict__ b_fc2,
              const float* __restrict__ lk,   const float* __restrict__ lb,
              const float* __restrict__ W_conv, const float* __restrict__ b_conv) {
    const int warp = threadIdx.x >> 5;
    const int lane = threadIdx.x & 31;
    const int b = blockIdx.x * 8 + warp;

    __shared__ float z2s[8][32];
    __shared__ float qs[8][32];

    // z2[lane] = b_fc2[lane] + sum_k M[b,k] * W_fc2[k,lane]
    float acc = b_fc2[lane];
    const float* Mrow = g_M + b * H256_;
#pragma unroll 4
    for (int k = 0; k < H256_; k++) acc += Mrow[k] * W_fc2[k * H32_ + lane];
    z2s[warp][lane] = acc;
    __syncwarp();

    // gates (f gate unused: f * c0 with c0 = 0)
    float zi = lb[lane];
    float zg = lb[64 + lane];
    float zo = lb[96 + lane];
#pragma unroll
    for (int m = 0; m < 32; m++) {
        float v = z2s[warp][m];
        zi += v * lk[m * 128 + lane];
        zg += v * lk[m * 128 + 64 + lane];
        zo += v * lk[m * 128 + 96 + lane];
    }
    float ig = 1.0f / (1.0f + expf(-zi));
    float gg = tanhf(zg);
    float og = 1.0f / (1.0f + expf(-zo));
    float c  = ig * gg;
    float h  = og * tanhf(c);
    qs[warp][lane] = h;
    __syncwarp();

    // c0 = b_conv . query
    float part = b_conv[lane] * h;
#pragma unroll
    for (int s = 16; s > 0; s >>= 1) part += __shfl_xor_sync(0xffffffffu, part, s);
    if (lane == 0) g_c0[b] = part;

    // w[d] = W_conv[d,:] . query
    for (int d = lane; d < EMB_; d += 32) {
        float a2 = 0.0f;
#pragma unroll
        for (int m = 0; m < 32; m++) a2 += W_conv[d * H32_ + m] * qs[warp][m];
        g_w[b * EMB_ + d] = a2;
    }
}

// ---------------------------------------------------------------------------
// Kernel B: per-b block: y[e] = ee[b,e,:] . w[b] + c0[b]  (512 rows, 256-dot),
// softmax, probs + gumbel argmax (threefry key 42), masked writes.
// mode: 0 = logits only; 1 = ids appended as float; 2 = ids appended as int64.
// ---------------------------------------------------------------------------
__global__ __launch_bounds__(256)
void kernelB(const float* __restrict__ ee, const int* __restrict__ tum,
             float* __restrict__ out, int mode) {
    const int b = blockIdx.x;
    const int tid = threadIdx.x;
    const int warp = tid >> 5;
    const int lane = tid & 31;

    __shared__ float ys[512];
    __shared__ float redv[256];
    __shared__ int   redi[256];

    const float* wb = g_w + b * EMB_;
    const float4 w0 = *(const float4*)(wb + 4 * lane);
    const float4 w1 = *(const float4*)(wb + 128 + 4 * lane);
    const float cb = g_c0[b];
    const float4* eb = (const float4*)(ee + (size_t)b * E_ * EMB_);

    for (int e = warp; e < 512; e += 16) {
        const int e2 = e + 8;
        float4 a0 = eb[(size_t)e * 64 + lane];
        float4 a1 = eb[(size_t)e * 64 + 32 + lane];
        float4 c0v = eb[(size_t)e2 * 64 + lane];
        float4 c1v = eb[(size_t)e2 * 64 + 32 + lane];
        float s0 = a0.x * w0.x + a0.y * w0.y + a0.z * w0.z + a0.w * w0.w
                 + a1.x * w1.x + a1.y * w1.y + a1.z * w1.z + a1.w * w1.w;
        float s1 = c0v.x * w0.x + c0v.y * w0.y + c0v.z * w0.z + c0v.w * w0.w
                 + c1v.x * w1.x + c1v.y * w1.y + c1v.z * w1.z + c1v.w * w1.w;
#pragma unroll
        for (int o = 16; o > 0; o >>= 1) {
            s0 += __shfl_xor_sync(0xffffffffu, s0, o);
            s1 += __shfl_xor_sync(0xffffffffu, s1, o);
        }
        if (lane == 0) { ys[e] = s0 + cb; ys[e2] = s1 + cb; }
    }
    __syncthreads();

    // row max
    float m = fmaxf(ys[tid], ys[tid + 256]);
    redv[tid] = m;
    __syncthreads();
    for (int s = 128; s > 0; s >>= 1) {
        if (tid < s) redv[tid] = fmaxf(redv[tid], redv[tid + s]);
        __syncthreads();
    }
    const float maxv = redv[0];
    __syncthreads();

    // exp + sum
    float e0 = expf(ys[tid] - maxv);
    float e1 = expf(ys[tid + 256] - maxv);
    redv[tid] = e0 + e1;
    __syncthreads();
    for (int s = 128; s > 0; s >>= 1) {
        if (tid < s) redv[tid] += redv[tid + s];
        __syncthreads();
    }
    const float sumv = redv[0];
    __syncthreads();

    // probs + gumbel, argmax with first-index tie-break
    float p0 = e0 / sumv;
    float p1 = e1 / sumv;
    float s0 = p0 + gumbel_from_index((uint32_t)(b * 512 + tid));
    float s1 = p1 + gumbel_from_index((uint32_t)(b * 512 + tid + 256));
    float bv; int bi;
    if (s1 > s0) { bv = s1; bi = tid + 256; } else { bv = s0; bi = tid; }
    redv[tid] = bv; redi[tid] = bi;
    __syncthreads();
    for (int s = 128; s > 0; s >>= 1) {
        if (tid < s) {
            float ov = redv[tid + s]; int oi = redi[tid + s];
            if (ov > redv[tid] || (ov == redv[tid] && oi < redi[tid])) {
                redv[tid] = ov; redi[tid] = oi;
            }
        }
        __syncthreads();
    }

    const int tm = tum[b];
    const float mf = (float)tm;
    out[(size_t)b * 512 + tid]       = ys[tid] * mf;
    out[(size_t)b * 512 + tid + 256] = ys[tid + 256] * mf;
    if (tid == 0 && mode != 0) {
        long long id = (long long)redi[0] * (long long)tm;
        if (mode == 1) out[1048576 + b] = (float)id;
        else ((long long*)(out + 1048576))[b] = id;
    }
}

// ---------------------------------------------------------------------------
extern "C" void kernel_launch(void* const* d_in, const int* in_sizes, int n_in,
                              void* d_out, int out_size) {
    const float* ar     = (const float*)d_in[0];
    const int*   utm    = (const int*)d_in[1];
    const int*   tum    = (const int*)d_in[2];
    const float* ee     = (const float*)d_in[3];
    const float* W_func = (const float*)d_in[4];
    const float* b_func = (const float*)d_in[5];
    const float* W_conv = (const float*)d_in[6];
    const float* b_conv = (const float*)d_in[7];
    const float* W_fc1  = (const float*)d_in[8];
    const float* b_fc1  = (const float*)d_in[9];
    const float* W_fc2  = (const float*)d_in[10];
    const float* b_fc2  = (const float*)d_in[11];
    const float* lk     = (const float*)d_in[12];
    // d_in[13] = lstm_recurrent: unused (h0 = 0)
    const float* lb     = (const float*)d_in[14];

    kernelA1<<<dim3(32, 4), 256>>>(ar, utm, W_func, b_func, W_fc1, b_fc1);
    kernelA2<<<256, 256>>>(W_fc2, b_fc2, lk, lb, W_conv, b_conv);

    int mode = 0;
    if (out_size >= 1048576 + 4096)      mode = 2;  // int64 ids appended
    else if (out_size >= 1048576 + 2048) mode = 1;  // float ids appended
    kernelB<<<2048, 256>>>(ee, tum, (float*)d_out, mode);
}

// round 2
// speedup vs baseline: 1.3754x; 1.3754x over previous
#include <cuda_runtime.h>
#include <cstdint>
#include <cstddef>

#define B_   2048
#define E_   512
#define EMB_ 256
#define AR_  1024
#define H256_ 256
#define H32_  32
#define NT_   256

// Scratch (no cudaMalloc allowed)
__device__ float g_T[B_ * H256_];    // relu(mask@W_func + b_func)
__device__ float g_W12[AR_ * H32_];  // W_fc1 @ W_fc2
__device__ float g_bvec[H32_];       // b_fc1 @ W_fc2 + b_fc2
__device__ float g_w[B_ * EMB_];     // W_conv @ query[b]
__device__ float g_c0[B_];           // b_conv . query[b]

// ---------------------------------------------------------------------------
// Threefry2x32-20, JAX partitionable variant: counter (hi=0, lo=index),
// output = out0 ^ out1, key = (0, 42).
// ---------------------------------------------------------------------------
__device__ __forceinline__ uint32_t rotl32(uint32_t x, int r) {
    return (x << r) | (x >> (32 - r));
}

__device__ __forceinline__ uint32_t threefry_bits(uint32_t k0, uint32_t k1,
                                                  uint32_t c0, uint32_t c1) {
    uint32_t ks2 = k0 ^ k1 ^ 0x1BD11BDAu;
    uint32_t x0 = c0 + k0;
    uint32_t x1 = c1 + k1;
#define TF_RND(r) { x0 += x1; x1 = rotl32(x1, (r)); x1 ^= x0; }
    TF_RND(13) TF_RND(15) TF_RND(26) TF_RND(6)
    x0 += k1;  x1 += ks2 + 1u;
    TF_RND(17) TF_RND(29) TF_RND(16) TF_RND(24)
    x0 += ks2; x1 += k0 + 2u;
    TF_RND(13) TF_RND(15) TF_RND(26) TF_RND(6)
    x0 += k0;  x1 += k1 + 3u;
    TF_RND(17) TF_RND(29) TF_RND(16) TF_RND(24)
    x0 += k1;  x1 += ks2 + 4u;
    TF_RND(13) TF_RND(15) TF_RND(26) TF_RND(6)
    x0 += ks2; x1 += k0 + 5u;
#undef TF_RND
    return x0 ^ x1;
}

__device__ __forceinline__ float gumbel_from_index(uint32_t idx) {
    uint32_t bits = threefry_bits(0u, 42u, 0u, idx);
    float u = __uint_as_float((bits >> 9) | 0x3f800000u) - 1.0f;
    const float tiny = 1.17549435e-38f;
    u = fmaxf(tiny, u + tiny);
    return -logf(-logf(u));
}

// ---------------------------------------------------------------------------
// P0: g_W12 = W_fc1 @ W_fc2 (1024x32), g_bvec = b_fc1 @ W_fc2 + b_fc2.
// One warp per output row; W_fc2 staged in smem.
// ---------------------------------------------------------------------------
__global__ __launch_bounds__(256)
void kernelP0(const float* __restrict__ W_fc1, const float* __restrict__ W_fc2,
              const float* __restrict__ b_fc1, const float* __restrict__ b_fc2) {
    __shared__ float s_w2[H256_ * H32_];   // 32KB
    const int tid = threadIdx.x;
    const int warp = tid >> 5, lane = tid & 31;
    for (int i = tid; i < H256_ * H32_; i += 256) s_w2[i] = W_fc2[i];
    __syncthreads();

    const int r = blockIdx.x * 8 + warp;
    const float* frow = W_fc1 + r * H256_;
    float a0 = 0.f, a1 = 0.f, a2 = 0.f, a3 = 0.f;
#pragma unroll 8
    for (int k0 = 0; k0 < H256_; k0 += 4) {
        float4 f = *(const float4*)(frow + k0);
        a0 += f.x * s_w2[(k0 + 0) * H32_ + lane];
        a1 += f.y * s_w2[(k0 + 1) * H32_ + lane];
        a2 += f.z * s_w2[(k0 + 2) * H32_ + lane];
        a3 += f.w * s_w2[(k0 + 3) * H32_ + lane];
    }
    g_W12[r * H32_ + lane] = (a0 + a1) + (a2 + a3);

    if (blockIdx.x == 0 && warp == 0) {
        float b0 = b_fc2[lane];
#pragma unroll 8
        for (int k = 0; k < H256_; k++) b0 += b_fc1[k] * s_w2[k * H32_ + lane];
        g_bvec[lane] = b0;
    }
}

// ---------------------------------------------------------------------------
// Q1: g_T = relu(maskf @ W_func + b_func). BM=64, BN=64, BK=16.
// ---------------------------------------------------------------------------
__global__ __launch_bounds__(256)
void kernelQ1(const int* __restrict__ utm, const float* __restrict__ W_func,
              const float* __restrict__ b_func) {
    __shared__ float As[16][68];
    __shared__ float Bs[16][64];

    const int bm = blockIdx.x * 64;
    const int bn = blockIdx.y * 64;
    const int tid = threadIdx.x;
    const int tx = tid & 15;
    const int ty = tid >> 4;

    const int lAm = tid >> 2;
    const int lAk = (tid & 3) * 4;
    const int lBk = tid >> 4;
    const int lBn = (tid & 15) * 4;

    float acc[4][4];
#pragma unroll
    for (int i = 0; i < 4; i++)
#pragma unroll
        for (int j = 0; j < 4; j++) acc[i][j] = 0.0f;

    for (int k0 = 0; k0 < NT_; k0 += 16) {
        int4 mi = *(const int4*)(utm + (bm + lAm) * NT_ + k0 + lAk);
        As[lAk + 0][lAm] = (float)mi.x;
        As[lAk + 1][lAm] = (float)mi.y;
        As[lAk + 2][lAm] = (float)mi.z;
        As[lAk + 3][lAm] = (float)mi.w;
        *(float4*)&Bs[lBk][lBn] = *(const float4*)(W_func + (k0 + lBk) * H256_ + bn + lBn);
        __syncthreads();
#pragma unroll
        for (int kk = 0; kk < 16; kk++) {
            float a[4], bb[4];
            *(float4*)a  = *(const float4*)&As[kk][ty * 4];
            *(float4*)bb = *(const float4*)&Bs[kk][tx * 4];
#pragma unroll
            for (int i = 0; i < 4; i++)
#pragma unroll
                for (int j = 0; j < 4; j++) acc[i][j] += a[i] * bb[j];
        }
        __syncthreads();
    }

#pragma unroll
    for (int j = 0; j < 4; j++) {
        float bf = b_func[bn + tx * 4 + j];
#pragma unroll
        for (int i = 0; i < 4; i++)
            g_T[(bm + ty * 4 + i) * H256_ + bn + tx * 4 + j] =
                fmaxf(acc[i][j] + bf, 0.0f);
    }
}

// ---------------------------------------------------------------------------
// QF: one warp per b. z2 = T[b]@W_fc2 + ar[b]@W12 + bvec; LSTM step (h0=c0=0);
//     g_w[b] = W_conv @ query; g_c0[b] = b_conv . query.
// ---------------------------------------------------------------------------
__global__ __launch_bounds__(256)
void kernelQF(const float* __restrict__ ar, const float* __restrict__ W_fc2,
              const float* __restrict__ lk, const float* __restrict__ lb,
              const float* __restrict__ W_conv, const float* __restrict__ b_conv) {
    const int warp = threadIdx.x >> 5;
    const int lane = threadIdx.x & 31;
    const int b = blockIdx.x * 8 + warp;

    __shared__ float z2s[8][32];
    __shared__ float qs[8][32];

    float a0 = 0.f, a1 = 0.f, a2 = 0.f, a3 = 0.f;
    const float* Trow = g_T + b * H256_;
#pragma unroll 8
    for (int k0 = 0; k0 < H256_; k0 += 4) {
        float4 t = *(const float4*)(Trow + k0);
        a0 += t.x * W_fc2[(k0 + 0) * H32_ + lane];
        a1 += t.y * W_fc2[(k0 + 1) * H32_ + lane];
        a2 += t.z * W_fc2[(k0 + 2) * H32_ + lane];
        a3 += t.w * W_fc2[(k0 + 3) * H32_ + lane];
    }
    const float* arow = ar + (size_t)b * AR_;
#pragma unroll 8
    for (int r0 = 0; r0 < AR_; r0 += 4) {
        float4 a = *(const float4*)(arow + r0);
        a0 += a.x * g_W12[(r0 + 0) * H32_ + lane];
        a1 += a.y * g_W12[(r0 + 1) * H32_ + lane];
        a2 += a.z * g_W12[(r0 + 2) * H32_ + lane];
        a3 += a.w * g_W12[(r0 + 3) * H32_ + lane];
    }
    z2s[warp][lane] = g_bvec[lane] + (a0 + a1) + (a2 + a3);
    __syncwarp();

    // gates (f gate unused: c0 = 0)
    float zi = lb[lane];
    float zg = lb[64 + lane];
    float zo = lb[96 + lane];
#pragma unroll
    for (int m = 0; m < 32; m++) {
        float v = z2s[warp][m];
        zi += v * lk[m * 128 + lane];
        zg += v * lk[m * 128 + 64 + lane];
        zo += v * lk[m * 128 + 96 + lane];
    }
    float ig = 1.0f / (1.0f + expf(-zi));
    float gg = tanhf(zg);
    float og = 1.0f / (1.0f + expf(-zo));
    float c  = ig * gg;
    float h  = og * tanhf(c);
    qs[warp][lane] = h;
    __syncwarp();

    // c0 = b_conv . query
    float part = b_conv[lane] * h;
#pragma unroll
    for (int s = 16; s > 0; s >>= 1) part += __shfl_xor_sync(0xffffffffu, part, s);
    if (lane == 0) g_c0[b] = part;

    // w[d] = W_conv[d,:] . query
#pragma unroll
    for (int d0 = 0; d0 < EMB_; d0 += 32) {
        const int d = d0 + lane;
        const float* wr = W_conv + d * H32_;
        float s0 = 0.f, s1 = 0.f;
#pragma unroll
        for (int m = 0; m < 32; m += 4) {
            float4 wc = *(const float4*)(wr + m);
            s0 += wc.x * qs[warp][m + 0] + wc.y * qs[warp][m + 1];
            s1 += wc.z * qs[warp][m + 2] + wc.w * qs[warp][m + 3];
        }
        g_w[b * EMB_ + d] = s0 + s1;
    }
}

// ---------------------------------------------------------------------------
// Kernel B: per-b block. y[e] = ee[b,e,:].w[b] + c0[b]; softmax; probs+gumbel
// argmax; masked writes. 4 rows per warp iteration for MLP; __ldcs streaming.
// ---------------------------------------------------------------------------
__global__ __launch_bounds__(256)
void kernelB(const float* __restrict__ ee, const int* __restrict__ tum,
             float* __restrict__ out, int mode) {
    const int b = blockIdx.x;
    const int tid = threadIdx.x;
    const int warp = tid >> 5;
    const int lane = tid & 31;

    __shared__ float ys[512];
    __shared__ float redv[256];
    __shared__ int   redi[256];

    const float* wb = g_w + b * EMB_;
    const float4 w0 = *(const float4*)(wb + 4 * lane);
    const float4 w1 = *(const float4*)(wb + 128 + 4 * lane);
    const float cb = g_c0[b];
    const float4* eb = (const float4*)(ee + (size_t)b * E_ * EMB_);

#pragma unroll
    for (int it = 0; it < 16; it++) {
        const int e0 = it * 32 + warp * 4;
        // 8 independent LDG.128 per lane, streaming
        float4 r0a = __ldcs(eb + (size_t)(e0 + 0) * 64 + lane);
        float4 r0b = __ldcs(eb + (size_t)(e0 + 0) * 64 + 32 + lane);
        float4 r1a = __ldcs(eb + (size_t)(e0 + 1) * 64 + lane);
        float4 r1b = __ldcs(eb + (size_t)(e0 + 1) * 64 + 32 + lane);
        float4 r2a = __ldcs(eb + (size_t)(e0 + 2) * 64 + lane);
        float4 r2b = __ldcs(eb + (size_t)(e0 + 2) * 64 + 32 + lane);
        float4 r3a = __ldcs(eb + (size_t)(e0 + 3) * 64 + lane);
        float4 r3b = __ldcs(eb + (size_t)(e0 + 3) * 64 + 32 + lane);

        float s0 = r0a.x * w0.x + r0a.y * w0.y + r0a.z * w0.z + r0a.w * w0.w
                 + r0b.x * w1.x + r0b.y * w1.y + r0b.z * w1.z + r0b.w * w1.w;
        float s1 = r1a.x * w0.x + r1a.y * w0.y + r1a.z * w0.z + r1a.w * w0.w
                 + r1b.x * w1.x + r1b.y * w1.y + r1b.z * w1.z + r1b.w * w1.w;
        float s2 = r2a.x * w0.x + r2a.y * w0.y + r2a.z * w0.z + r2a.w * w0.w
                 + r2b.x * w1.x + r2b.y * w1.y + r2b.z * w1.z + r2b.w * w1.w;
        float s3 = r3a.x * w0.x + r3a.y * w0.y + r3a.z * w0.z + r3a.w * w0.w
                 + r3b.x * w1.x + r3b.y * w1.y + r3b.z * w1.z + r3b.w * w1.w;
#pragma unroll
        for (int o = 16; o > 0; o >>= 1) {
            s0 += __shfl_xor_sync(0xffffffffu, s0, o);
            s1 += __shfl_xor_sync(0xffffffffu, s1, o);
            s2 += __shfl_xor_sync(0xffffffffu, s2, o);
            s3 += __shfl_xor_sync(0xffffffffu, s3, o);
        }
        if (lane == 0) {
            ys[e0 + 0] = s0 + cb;
            ys[e0 + 1] = s1 + cb;
            ys[e0 + 2] = s2 + cb;
            ys[e0 + 3] = s3 + cb;
        }
    }
    __syncthreads();

    // row max
    float m = fmaxf(ys[tid], ys[tid + 256]);
    redv[tid] = m;
    __syncthreads();
    for (int s = 128; s > 0; s >>= 1) {
        if (tid < s) redv[tid] = fmaxf(redv[tid], redv[tid + s]);
        __syncthreads();
    }
    const float maxv = redv[0];
    __syncthreads();

    // exp + sum
    float e0v = expf(ys[tid] - maxv);
    float e1v = expf(ys[tid + 256] - maxv);
    redv[tid] = e0v + e1v;
    __syncthreads();
    for (int s = 128; s > 0; s >>= 1) {
        if (tid < s) redv[tid] += redv[tid + s];
        __syncthreads();
    }
    const float sumv = redv[0];
    __syncthreads();

    // probs + gumbel, argmax with first-index tie-break
    float p0 = e0v / sumv;
    float p1 = e1v / sumv;
    float s0 = p0 + gumbel_from_index((uint32_t)(b * 512 + tid));
    float s1 = p1 + gumbel_from_index((uint32_t)(b * 512 + tid + 256));
    float bv; int bi;
    if (s1 > s0) { bv = s1; bi = tid + 256; } else { bv = s0; bi = tid; }
    redv[tid] = bv; redi[tid] = bi;
    __syncthreads();
    for (int s = 128; s > 0; s >>= 1) {
        if (tid < s) {
            float ov = redv[tid + s]; int oi = redi[tid + s];
            if (ov > redv[tid] || (ov == redv[tid] && oi < redi[tid])) {
                redv[tid] = ov; redi[tid] = oi;
            }
        }
        __syncthreads();
    }

    const int tm = tum[b];
    const float mf = (float)tm;
    out[(size_t)b * 512 + tid]       = ys[tid] * mf;
    out[(size_t)b * 512 + tid + 256] = ys[tid + 256] * mf;
    if (tid == 0 && mode != 0) {
        long long id = (long long)redi[0] * (long long)tm;
        if (mode == 1) out[1048576 + b] = (float)id;
        else ((long long*)(out + 1048576))[b] = id;
    }
}

// ---------------------------------------------------------------------------
extern "C" void kernel_launch(void* const* d_in, const int* in_sizes, int n_in,
                              void* d_out, int out_size) {
    const float* ar     = (const float*)d_in[0];
    const int*   utm    = (const int*)d_in[1];
    const int*   tum    = (const int*)d_in[2];
    const float* ee     = (const float*)d_in[3];
    const float* W_func = (const float*)d_in[4];
    const float* b_func = (const float*)d_in[5];
    const float* W_conv = (const float*)d_in[6];
    const float* b_conv = (const float*)d_in[7];
    const float* W_fc1  = (const float*)d_in[8];
    const float* b_fc1  = (const float*)d_in[9];
    const float* W_fc2  = (const float*)d_in[10];
    const float* b_fc2  = (const float*)d_in[11];
    const float* lk     = (const float*)d_in[12];
    // d_in[13] = lstm_recurrent: unused (h0 = 0)
    const float* lb     = (const float*)d_in[14];

    kernelP0<<<128, 256>>>(W_fc1, W_fc2, b_fc1, b_fc2);
    kernelQ1<<<dim3(32, 4), 256>>>(utm, W_func, b_func);
    kernelQF<<<256, 256>>>(ar, W_fc2, lk, lb, W_conv, b_conv);

    int mode = 0;
    if (out_size >= 1048576 + 4096)      mode = 2;
    else if (out_size >= 1048576 + 2048) mode = 1;
    kernelB<<<2048, 256>>>(ee, tum, (float*)d_out, mode);
}